// round 13
// baseline (speedup 1.0000x reference)
#include <cuda_runtime.h>
#include <cuda_bf16.h>
#include <cstdint>
#include <cstddef>

// Problem constants
static constexpr int Bn = 4;
static constexpr int Sn = 2048;
static constexpr int En = 1024;
static constexpr int Hn = 16;
static constexpr int Dn = 64;

// Scratch (device globals; no cudaMalloc allowed)
__device__ float g_qkv[(size_t)Bn * Sn * 3 * En];   // [B,S,3E]

// Pre-split bf16 hi/lo operand tiles (fragment-major layout)
__device__ uint4 g_xh[1048576], g_xl[1048576];      // x:    [64][32] tiles
__device__ uint4 g_ah[1048576], g_al[1048576];      // attn out (written by attn epilogue)
__device__ uint4 g_wih[393216], g_wil[393216];      // w_in
__device__ uint4 g_woh[131072], g_wol[131072];      // w_out

__device__ __forceinline__ float tf32_rna(float x) {
    uint32_t u;
    asm("cvt.rna.tf32.f32 %0, %1;" : "=r"(u) : "f"(x));
    return __uint_as_float(u);
}

__device__ __forceinline__ float ex2(float x) {
    float y;
    asm("ex2.approx.ftz.f32 %0, %1;" : "=f"(y) : "f"(x));
    return y;
}

__device__ __forceinline__ void mma_tf32(float* c, const uint32_t* a, const uint32_t* b) {
    asm volatile(
        "mma.sync.aligned.m16n8k8.row.col.f32.tf32.tf32.f32 "
        "{%0,%1,%2,%3}, {%4,%5,%6,%7}, {%8,%9}, {%0,%1,%2,%3};"
        : "+f"(c[0]), "+f"(c[1]), "+f"(c[2]), "+f"(c[3])
        : "r"(a[0]), "r"(a[1]), "r"(a[2]), "r"(a[3]), "r"(b[0]), "r"(b[1]));
}

__device__ __forceinline__ void mma_bf16(float* c, const uint32_t* a, const uint32_t* b) {
    asm volatile(
        "mma.sync.aligned.m16n8k16.row.col.f32.bf16.bf16.f32 "
        "{%0,%1,%2,%3}, {%4,%5,%6,%7}, {%8,%9}, {%0,%1,%2,%3};"
        : "+f"(c[0]), "+f"(c[1]), "+f"(c[2]), "+f"(c[3])
        : "r"(a[0]), "r"(a[1]), "r"(a[2]), "r"(a[3]), "r"(b[0]), "r"(b[1]));
}

__device__ __forceinline__ void split_pack_bf16(float x0, float x1,
                                                uint32_t& hi, uint32_t& lo) {
    __nv_bfloat162 h = __floats2bfloat162_rn(x0, x1);
    float f0 = __bfloat162float(h.x);
    float f1 = __bfloat162float(h.y);
    __nv_bfloat162 l = __floats2bfloat162_rn(x0 - f0, x1 - f1);
    hi = *(uint32_t*)&h;
    lo = *(uint32_t*)&l;
}

__device__ __forceinline__ void cp16(uint32_t dst, const void* src) {
    asm volatile("cp.async.ca.shared.global [%0], [%1], 16;"
                 :: "r"(dst), "l"(src) : "memory");
}

#define MBARRIER_INIT(addr, count) \
    asm volatile("mbarrier.init.shared.b64 [%0], %1;" :: "r"((uint32_t)(addr)), "r"((uint32_t)(count)) : "memory")
#define MBARRIER_ARRIVE(addr) \
    asm volatile("mbarrier.arrive.shared.b64 _, [%0];" :: "r"((uint32_t)(addr)) : "memory")
#define MBARRIER_WAIT_PARITY(addr, parity) do { \
    uint32_t _m = (uint32_t)(addr); uint32_t _p = (uint32_t)(parity); uint32_t _d; \
    asm volatile("{\n\t.reg .pred p;\n\t" \
        "mbarrier.try_wait.parity.acquire.cta.shared::cta.b64 p, [%1], %2;\n\t" \
        "selp.b32 %0, 1, 0, p;\n\t}" : "=r"(_d) : "r"(_m), "r"(_p) : "memory"); \
    if (!_d) { \
        asm volatile("{\n\t.reg .pred P1;\n\t" \
            "WL_%=:\n\t" \
            "mbarrier.try_wait.parity.acquire.cta.shared::cta.b64 P1, [%0], %1, 0x989680;\n\t" \
            "@P1 bra.uni WD_%=;\n\tbra.uni WL_%=;\n\tWD_%=:\n\t}" \
            :: "r"(_m), "r"(_p) : "memory"); \
    } } while (0)

// ============================================================================
// Prep kernels (R10 proven): split fp32 -> bf16 hi/lo, fragment-major layout.
// ============================================================================
__global__ __launch_bounds__(256) void prep_a(
    const float* __restrict__ A, uint4* __restrict__ H, uint4* __restrict__ L, int K)
{
    const size_t o = (size_t)blockIdx.x * 256 + threadIdx.x;
    const int u4 = (int)(o & 511);
    const int tile = (int)(o >> 9);
    const int kT = K >> 5;
    const int mt = tile / kT, kt = tile % kT;
    const int blkPair = u4 >> 5;
    const int m16 = blkPair >> 1, kblk = blkPair & 1;
    const int rem = u4 & 31;
    const int g = rem >> 2, t4 = rem & 3;
    const int r0 = mt * 128 + m16 * 16 + g;
    const int kb = kt * 32 + kblk * 16 + t4 * 2;
    const float* p0 = A + (size_t)r0 * K + kb;
    const float* p1 = p0 + (size_t)8 * K;
    const float2 a00 = *(const float2*)p0;
    const float2 a10 = *(const float2*)p1;
    const float2 a01 = *(const float2*)(p0 + 8);
    const float2 a11 = *(const float2*)(p1 + 8);
    uint4 hv, lv;
    split_pack_bf16(a00.x, a00.y, hv.x, lv.x);
    split_pack_bf16(a10.x, a10.y, hv.y, lv.y);
    split_pack_bf16(a01.x, a01.y, hv.z, lv.z);
    split_pack_bf16(a11.x, a11.y, hv.w, lv.w);
    H[o] = hv; L[o] = lv;
}

__global__ __launch_bounds__(256) void prep_b(
    const float* __restrict__ B, uint4* __restrict__ H, uint4* __restrict__ L, int K)
{
    const size_t o = (size_t)blockIdx.x * 256 + threadIdx.x;
    const int u4 = (int)(o & 511);
    const int tile = (int)(o >> 9);
    const int kT = K >> 5;
    const int nt = tile / kT, kt = tile % kT;
    const int blkPair = u4 >> 4;
    const int nblk = blkPair >> 1, kblk = blkPair & 1;
    const int rem = u4 & 15;
    const int g = rem >> 1, j = rem & 1;
    const int n = nt * 128 + nblk * 8 + g;
    const int kb = kt * 32 + kblk * 16 + j * 4;
    const float4 p = *(const float4*)(B + (size_t)n * K + kb);
    const float4 q = *(const float4*)(B + (size_t)n * K + kb + 8);
    uint4 hv, lv;
    split_pack_bf16(p.x, p.y, hv.x, lv.x);
    split_pack_bf16(q.x, q.y, hv.y, lv.y);
    split_pack_bf16(p.z, p.w, hv.z, lv.z);
    split_pack_bf16(q.z, q.w, hv.w, lv.w);
    H[o] = hv; L[o] = lv;
}

// ============================================================================
// 3xBF16 tensor-core GEMM on pre-split fragment-major operands (R11 proven).
// ============================================================================
static constexpr int STAGE_E = 16384;
static constexpr int GEMM_SMEM = 3 * STAGE_E * 2;     // 98304 bytes

__global__ __launch_bounds__(256, 2) void gemm_pre(
    const uint4* __restrict__ AH, const uint4* __restrict__ AL,
    const uint4* __restrict__ BH, const uint4* __restrict__ BL,
    const float* __restrict__ bias, float* __restrict__ C,
    int N, int kT, int roundFromTile)
{
    extern __shared__ uint16_t smu[];
    const int tid = threadIdx.x;
    const int wid = tid >> 5;
    const int lane = tid & 31;
    const int g = lane >> 2;
    const int t4 = lane & 3;
    const int wm = wid >> 1;
    const int wn = wid & 1;
    const int mt = blockIdx.y;
    const int nt = blockIdx.x;
    const uint32_t smem_base = (uint32_t)__cvta_generic_to_shared(smu);

    const size_t atile = (size_t)mt * kT;
    const size_t btile = (size_t)nt * kT;

    auto issue = [&](int j, int st) {
        const uint32_t dst0 = smem_base + st * 32768;
#pragma unroll
        for (int s = 0; s < 8; s++) {
            const int arr = s >> 1;
            const int off = tid + (s & 1) * 256;
            const uint4* bp = (arr == 0) ? AH : (arr == 1) ? AL
                             : (arr == 2) ? BH : BL;
            const size_t tb = (arr < 2) ? atile : btile;
            cp16(dst0 + arr * 8192 + off * 16, bp + (tb + j) * 512 + off);
        }
        asm volatile("cp.async.commit_group;" ::: "memory");
    };

    float acc[2][8][4];
#pragma unroll
    for (int mtl = 0; mtl < 2; mtl++)
#pragma unroll
        for (int ntl = 0; ntl < 8; ntl++)
#pragma unroll
            for (int i = 0; i < 4; i++) acc[mtl][ntl][i] = 0.f;

    issue(0, 0);
    issue(1, 1);

    for (int j = 0; j < kT; j++) {
        if (j + 1 < kT) {
            asm volatile("cp.async.wait_group 1;" ::: "memory");
        } else {
            asm volatile("cp.async.wait_group 0;" ::: "memory");
        }
        __syncthreads();
        if (j + 2 < kT) issue(j + 2, (j + 2) % 3);

        const uint16_t* stg = smu + (j % 3) * STAGE_E;
#pragma unroll
        for (int kblk = 0; kblk < 2; kblk++) {
            uint4 ahi[2], alo[2];
#pragma unroll
            for (int mtl = 0; mtl < 2; mtl++) {
                const int mblk = wm * 2 + mtl;
                const int base = (mblk * 2 + kblk) * 256 + g * 32 + t4 * 8;
                ahi[mtl] = *(const uint4*)(stg + base);
                alo[mtl] = *(const uint4*)(stg + 4096 + base);
            }
#pragma unroll
            for (int ntl = 0; ntl < 8; ntl++) {
                const int nblk = wn * 8 + ntl;
                const int bbase = (nblk * 2 + kblk) * 128 + g * 16 + t4 * 4;
                uint2 bh = *(const uint2*)(stg + 8192 + bbase);
                uint2 bl = *(const uint2*)(stg + 12288 + bbase);
#pragma unroll
                for (int mtl = 0; mtl < 2; mtl++) {
                    mma_bf16(acc[mtl][ntl], (const uint32_t*)&ahi[mtl], (const uint32_t*)&bh);
                    mma_bf16(acc[mtl][ntl], (const uint32_t*)&ahi[mtl], (const uint32_t*)&bl);
                    mma_bf16(acc[mtl][ntl], (const uint32_t*)&alo[mtl], (const uint32_t*)&bh);
                }
            }
        }
    }

    const bool roundT = (nt >= roundFromTile);
    const int bm = mt * 128;
    const int bn = nt * 128;
#pragma unroll
    for (int mtl = 0; mtl < 2; mtl++) {
        const int r0 = bm + wm * 32 + mtl * 16 + g;
#pragma unroll
        for (int ntl = 0; ntl < 8; ntl++) {
            const int c0 = bn + wn * 64 + ntl * 8 + t4 * 2;
            const float b0 = bias[c0];
            const float b1 = bias[c0 + 1];
            float2 v0, v1;
            v0.x = acc[mtl][ntl][0] + b0; v0.y = acc[mtl][ntl][1] + b1;
            v1.x = acc[mtl][ntl][2] + b0; v1.y = acc[mtl][ntl][3] + b1;
            if (roundT) {
                v0.x = tf32_rna(v0.x); v0.y = tf32_rna(v0.y);
                v1.x = tf32_rna(v1.x); v1.y = tf32_rna(v1.y);
            }
            *(float2*)(C + (size_t)r0 * N + c0) = v0;
            *(float2*)(C + (size_t)(r0 + 8) * N + c0) = v1;
        }
    }
}

// ============================================================================
// Flash attention: tf32 mma.sync, producer-warp mbarrier pipeline.
// Block = 160 threads: warps 0-3 compute 32 q-rows, warp 4 = producer.
// NEW: P in per-warp fragment-major float4 smem (LDS.128 reads);
//      base-2 softmax (log2e folded into Q scale, raw ex2.approx);
//      epilogue writes bf16 hi/lo split DIRECTLY in gemm fragment layout.
// ============================================================================
static constexpr int ABQ = 128, ABK = 32, APAD = 68;
static constexpr int QF0 = 32;
static constexpr int KV0 = QF0 + ABQ * APAD;            // 8736
static constexpr int PF0 = KV0 + 3 * 4352;              // 21792
// P: 4 warps x (2 mt x 4 kb x 32 lanes x 4) = 4 x 1024 floats
static constexpr int ATTN_SMEM = (PF0 + 4 * 1024) * 4;  // 103296 B

__global__ __launch_bounds__(160, 2) void attn_mma(
    const float* __restrict__ qkv,
    uint4* __restrict__ OH, uint4* __restrict__ OL)
{
    extern __shared__ float sm[];
    const int tid = threadIdx.x;
    const int wid = tid >> 5;
    const int lane = tid & 31;
    const int g = lane >> 2;
    const int t4 = lane & 3;
    const int qi = gridDim.x - 1 - blockIdx.x;
    const int h = blockIdx.y;
    const int b = blockIdx.z;
    const int q0 = qi * ABQ;
    const size_t rs = (size_t)3 * En;
    const float* qbase = qkv + (size_t)b * Sn * rs + (size_t)h * Dn;
    const float* kbase = qbase + En;
    const float* vbase = qbase + 2 * En;
    const uint32_t smem_base = (uint32_t)__cvta_generic_to_shared(sm);
    const int ntiles = 4 * qi + 4;

    if (tid == 0) {
#pragma unroll
        for (int s = 0; s < 3; s++) {
            MBARRIER_INIT(smem_base + s * 8, 32);
            MBARRIER_INIT(smem_base + 24 + s * 8, 4);
        }
    }

    // Q tile -> smem, scale = 0.125 * log2(e) (base-2 softmax), tf32-rna
    if (tid < 128) {
        const float qscale = 0.125f * 1.4426950408889634f;
        for (int i = tid; i < ABQ * 16; i += 128) {
            const int row = i >> 4, c4 = (i & 15) * 4;
            float4 v = *(const float4*)(qbase + (size_t)(q0 + row) * rs + c4);
            float4 hi;
            hi.x = tf32_rna(v.x * qscale);
            hi.y = tf32_rna(v.y * qscale);
            hi.z = tf32_rna(v.z * qscale);
            hi.w = tf32_rna(v.w * qscale);
            *(float4*)&sm[QF0 + row * APAD + c4] = hi;
        }
    }
    __syncthreads();

    if (tid >= 128) {
        // -------- producer warp --------
        for (int j = 0; j < ntiles; j++) {
            const int q3 = j / 3;
            const int s = j - 3 * q3;
            if (j >= 3) {
                MBARRIER_WAIT_PARITY(smem_base + 24 + s * 8, (q3 - 1) & 1);
            }
            const int k0 = j * ABK;
            const int base = KV0 + s * 4352;
#pragma unroll
            for (int c = 0; c < 32; c++) {
                const int i = c * 32 + lane;
                const int isV = i >> 9;
                const int ii = i & 511;
                const int row = ii >> 4, q = ii & 15;
                const float* src = (isV ? vbase : kbase) + (size_t)(k0 + row) * rs + q * 4;
                const int dstf = base + isV * 2176 + row * APAD + q * 4;
                cp16(smem_base + dstf * 4, src);
            }
            asm volatile("cp.async.commit_group;" ::: "memory");
            if (j >= 2) {
                asm volatile("cp.async.wait_group 2;" ::: "memory");
                MBARRIER_ARRIVE(smem_base + ((j - 2) % 3) * 8);
            }
        }
        asm volatile("cp.async.wait_group 1;" ::: "memory");
        MBARRIER_ARRIVE(smem_base + ((ntiles - 2) % 3) * 8);
        asm volatile("cp.async.wait_group 0;" ::: "memory");
        MBARRIER_ARRIVE(smem_base + ((ntiles - 1) % 3) * 8);
        return;
    }

    // -------- compute warps: 32 q-rows each --------
    float m_[2][2], l_[2][2];
#pragma unroll
    for (int mt = 0; mt < 2; mt++) {
        m_[mt][0] = -1e30f; m_[mt][1] = -1e30f;
        l_[mt][0] = 0.f;    l_[mt][1] = 0.f;
    }
    float o[2][8][4];
#pragma unroll
    for (int mt = 0; mt < 2; mt++)
#pragma unroll
        for (int nt = 0; nt < 8; nt++)
#pragma unroll
            for (int i = 0; i < 4; i++) o[mt][nt][i] = 0.f;

    const int wrow = wid * 32;
    float* Pw = sm + PF0 + wid * 1024;
    // P fragment write positions (per nt added later): lane' = g*4 + 2*(t4&1)
    const int pwl = (g * 4 + 2 * (t4 & 1)) * 4 + (t4 >> 1) * 2;

    for (int jt = 0; jt < ntiles; jt++) {
        const int q3 = jt / 3;
        const int s = jt - 3 * q3;
        const int k0 = jt * ABK;
        MBARRIER_WAIT_PARITY(smem_base + s * 8, q3 & 1);

        const float* Kb = sm + KV0 + s * 4352;
        const float* Vb = Kb + 2176;

        // ---- S = (Q*qscale) @ K^T ----
        float acc[2][4][4];
#pragma unroll
        for (int mt = 0; mt < 2; mt++)
#pragma unroll
            for (int nt = 0; nt < 4; nt++)
#pragma unroll
                for (int i = 0; i < 4; i++) acc[mt][nt][i] = 0.f;

#pragma unroll
        for (int kb = 0; kb < 8; kb++) {
            uint32_t aq[2][4];
#pragma unroll
            for (int mt = 0; mt < 2; mt++) {
                const int r = wrow + mt * 16 + g;
                aq[mt][0] = __float_as_uint(sm[QF0 + r * APAD + kb * 8 + t4]);
                aq[mt][1] = __float_as_uint(sm[QF0 + (r + 8) * APAD + kb * 8 + t4]);
                aq[mt][2] = __float_as_uint(sm[QF0 + r * APAD + kb * 8 + t4 + 4]);
                aq[mt][3] = __float_as_uint(sm[QF0 + (r + 8) * APAD + kb * 8 + t4 + 4]);
            }
#pragma unroll
            for (int nt = 0; nt < 4; nt++) {
                uint32_t bh[2];
                bh[0] = __float_as_uint(Kb[(nt * 8 + g) * APAD + kb * 8 + t4]);
                bh[1] = __float_as_uint(Kb[(nt * 8 + g) * APAD + kb * 8 + t4 + 4]);
#pragma unroll
                for (int mt = 0; mt < 2; mt++)
                    mma_tf32(acc[mt][nt], aq[mt], bh);
            }
        }

        // ---- causal mask ----
        if (jt >= ntiles - 4) {
#pragma unroll
            for (int mt = 0; mt < 2; mt++) {
                const int r0g = q0 + wrow + mt * 16 + g;
                const int r1g = r0g + 8;
#pragma unroll
                for (int nt = 0; nt < 4; nt++) {
                    const int c = k0 + nt * 8 + t4 * 2;
                    if (c > r0g)     acc[mt][nt][0] = -1e30f;
                    if (c + 1 > r0g) acc[mt][nt][1] = -1e30f;
                    if (c > r1g)     acc[mt][nt][2] = -1e30f;
                    if (c + 1 > r1g) acc[mt][nt][3] = -1e30f;
                }
            }
        }

        // ---- online softmax (base-2) ----
        float al[2][2];
#pragma unroll
        for (int mt = 0; mt < 2; mt++) {
            float mx0 = -1e30f, mx1 = -1e30f;
#pragma unroll
            for (int nt = 0; nt < 4; nt++) {
                mx0 = fmaxf(mx0, fmaxf(acc[mt][nt][0], acc[mt][nt][1]));
                mx1 = fmaxf(mx1, fmaxf(acc[mt][nt][2], acc[mt][nt][3]));
            }
            mx0 = fmaxf(mx0, __shfl_xor_sync(0xffffffffu, mx0, 1));
            mx0 = fmaxf(mx0, __shfl_xor_sync(0xffffffffu, mx0, 2));
            mx1 = fmaxf(mx1, __shfl_xor_sync(0xffffffffu, mx1, 1));
            mx1 = fmaxf(mx1, __shfl_xor_sync(0xffffffffu, mx1, 2));
            const float mn0 = fmaxf(m_[mt][0], mx0);
            const float mn1 = fmaxf(m_[mt][1], mx1);
            const float a0 = ex2(m_[mt][0] - mn0);
            const float a1 = ex2(m_[mt][1] - mn1);
            m_[mt][0] = mn0; m_[mt][1] = mn1;
            float s0 = 0.f, s1 = 0.f;
#pragma unroll
            for (int nt = 0; nt < 4; nt++) {
                acc[mt][nt][0] = ex2(acc[mt][nt][0] - mn0); s0 += acc[mt][nt][0];
                acc[mt][nt][1] = ex2(acc[mt][nt][1] - mn0); s0 += acc[mt][nt][1];
                acc[mt][nt][2] = ex2(acc[mt][nt][2] - mn1); s1 += acc[mt][nt][2];
                acc[mt][nt][3] = ex2(acc[mt][nt][3] - mn1); s1 += acc[mt][nt][3];
            }
            s0 += __shfl_xor_sync(0xffffffffu, s0, 1);
            s0 += __shfl_xor_sync(0xffffffffu, s0, 2);
            s1 += __shfl_xor_sync(0xffffffffu, s1, 1);
            s1 += __shfl_xor_sync(0xffffffffu, s1, 2);
            l_[mt][0] = l_[mt][0] * a0 + s0;
            l_[mt][1] = l_[mt][1] * a1 + s1;
            al[mt][0] = a0; al[mt][1] = a1;
        }

        // ---- P -> per-warp fragment-major smem (float2 stores) ----
#pragma unroll
        for (int mt = 0; mt < 2; mt++) {
#pragma unroll
            for (int nt = 0; nt < 4; nt++) {
                float2 w0, w1;
                w0.x = tf32_rna(acc[mt][nt][0]); w0.y = tf32_rna(acc[mt][nt][2]);
                w1.x = tf32_rna(acc[mt][nt][1]); w1.y = tf32_rna(acc[mt][nt][3]);
                float* pb = Pw + mt * 512 + nt * 128 + pwl;
                *(float2*)pb = w0;
                *(float2*)(pb + 4) = w1;
            }
        }
        __syncwarp();

        // ---- rescale O ----
#pragma unroll
        for (int mt = 0; mt < 2; mt++)
#pragma unroll
            for (int nt = 0; nt < 8; nt++) {
                o[mt][nt][0] *= al[mt][0]; o[mt][nt][1] *= al[mt][0];
                o[mt][nt][2] *= al[mt][1]; o[mt][nt][3] *= al[mt][1];
            }

        // ---- O += P @ V (A-fragments via single LDS.128) ----
#pragma unroll
        for (int kb = 0; kb < 4; kb++) {
            uint4 ap[2];
            ap[0] = *(const uint4*)&Pw[0 * 512 + kb * 128 + lane * 4];
            ap[1] = *(const uint4*)&Pw[1 * 512 + kb * 128 + lane * 4];
#pragma unroll
            for (int nt = 0; nt < 8; nt++) {
                uint32_t bh[2];
                bh[0] = __float_as_uint(Vb[(kb * 8 + t4) * APAD + nt * 8 + g]);
                bh[1] = __float_as_uint(Vb[(kb * 8 + t4 + 4) * APAD + nt * 8 + g]);
#pragma unroll
                for (int mt = 0; mt < 2; mt++)
                    mma_tf32(o[mt][nt], (const uint32_t*)&ap[mt], bh);
            }
        }
        __syncwarp();
        if (lane == 0) MBARRIER_ARRIVE(smem_base + 24 + s * 8);
    }

    // ---- normalize + write bf16 hi/lo split in gemm fragment layout ----
    // Element (row R, cols c0,c0+1) -> uint4 index tile*512+u4, comp pair.
#pragma unroll
    for (int mt = 0; mt < 2; mt++) {
        const float i0 = 1.f / l_[mt][0];
        const float i1 = 1.f / l_[mt][1];
        const int R0 = b * Sn + q0 + wrow + mt * 16 + g;   // global M row
        const int m16 = ((wrow + mt * 16) >> 4) & 7;
        const int tile_m = R0 >> 7;
#pragma unroll
        for (int nt = 0; nt < 8; nt++) {
            const int c0 = h * Dn + nt * 8 + t4 * 2;
            const int tile = tile_m * 32 + (c0 >> 5);
            const int kblk = (nt >> 1) & 1;
            const int khalf = nt & 1;
            const int u4i = (m16 * 2 + kblk) * 32 + g * 4 + t4;
            float v00 = o[mt][nt][0] * i0, v01 = o[mt][nt][1] * i0;
            float v10 = o[mt][nt][2] * i1, v11 = o[mt][nt][3] * i1;
            uint32_t h0, l0, h1, l1;
            split_pack_bf16(v00, v01, h0, l0);
            split_pack_bf16(v10, v11, h1, l1);
            uint2 hv; hv.x = h0; hv.y = h1;
            uint2 lv; lv.x = l0; lv.y = l1;
            const size_t oidx = (size_t)tile * 512 + u4i;
            *(uint2*)((uint32_t*)(OH + oidx) + khalf * 2) = hv;
            *(uint2*)((uint32_t*)(OL + oidx) + khalf * 2) = lv;
        }
    }
}

// ----------------------------------------------------------------------------
extern "C" void kernel_launch(void* const* d_in, const int* in_sizes, int n_in,
                              void* d_out, int out_size)
{
    const float* x     = (const float*)d_in[0];
    const float* w_in  = (const float*)d_in[1];
    const float* b_in  = (const float*)d_in[2];
    const float* w_out = (const float*)d_in[3];
    const float* b_out = (const float*)d_in[4];
    float* out = (float*)d_out;

    float* qkv;
    uint4 *xh, *xl, *ah, *al, *wih, *wil, *woh, *wol;
    cudaGetSymbolAddress((void**)&qkv, g_qkv);
    cudaGetSymbolAddress((void**)&xh, g_xh);
    cudaGetSymbolAddress((void**)&xl, g_xl);
    cudaGetSymbolAddress((void**)&ah, g_ah);
    cudaGetSymbolAddress((void**)&al, g_al);
    cudaGetSymbolAddress((void**)&wih, g_wih);
    cudaGetSymbolAddress((void**)&wil, g_wil);
    cudaGetSymbolAddress((void**)&woh, g_woh);
    cudaGetSymbolAddress((void**)&wol, g_wol);

    static bool attr_set = false;
    if (!attr_set) {
        cudaFuncSetAttribute(gemm_pre, cudaFuncAttributeMaxDynamicSharedMemorySize,
                             GEMM_SMEM);
        cudaFuncSetAttribute(attn_mma, cudaFuncAttributeMaxDynamicSharedMemorySize,
                             ATTN_SMEM);
        attr_set = true;
    }

    // 0) Pre-split operands into fragment-major bf16 hi/lo
    prep_a<<<4096, 256>>>(x, xh, xl, En);
    prep_b<<<1536, 256>>>(w_in, wih, wil, En);

    // 1) QKV projection; K/V columns (tiles >= 8) pre-rounded to tf32
    {
        dim3 grid(24, 64);
        gemm_pre<<<grid, 256, GEMM_SMEM>>>(xh, xl, wih, wil, b_in, qkv,
                                           3 * En, En / 32, 8);
    }

    // 2) Causal flash attention; epilogue writes hi/lo split directly
    {
        dim3 grid(Sn / ABQ, Hn, Bn);
        attn_mma<<<grid, 160, ATTN_SMEM>>>(qkv, ah, al);
    }

    // 3) Output projection (reads attn's fused hi/lo output)
    prep_b<<<512, 256>>>(w_out, woh, wol, En);
    {
        dim3 grid(8, 64);
        gemm_pre<<<grid, 256, GEMM_SMEM>>>(ah, al, woh, wol, b_out, out,
                                           En, En / 32, 1 << 30);
    }
}

// round 14
// speedup vs baseline: 1.5169x; 1.5169x over previous
#include <cuda_runtime.h>
#include <cuda_bf16.h>
#include <cstdint>
#include <cstddef>

// Problem constants
static constexpr int Bn = 4;
static constexpr int Sn = 2048;
static constexpr int En = 1024;
static constexpr int Hn = 16;
static constexpr int Dn = 64;

// Scratch (device globals; no cudaMalloc allowed)
__device__ float g_qkv[(size_t)Bn * Sn * 3 * En];   // [B,S,3E]
__device__ float g_attn[(size_t)Bn * Sn * En];      // [B,S,E]

// Pre-split bf16 hi/lo operand tiles (fragment-major layout)
__device__ uint4 g_xh[1048576], g_xl[1048576];      // x
__device__ uint4 g_ah[1048576], g_al[1048576];      // attn
__device__ uint4 g_wih[393216], g_wil[393216];      // w_in
__device__ uint4 g_woh[131072], g_wol[131072];      // w_out

__device__ __forceinline__ float tf32_rna(float x) {
    uint32_t u;
    asm("cvt.rna.tf32.f32 %0, %1;" : "=r"(u) : "f"(x));
    return __uint_as_float(u);
}

__device__ __forceinline__ float ex2(float x) {
    float y;
    asm("ex2.approx.ftz.f32 %0, %1;" : "=f"(y) : "f"(x));
    return y;
}

__device__ __forceinline__ void mma_tf32(float* c, const uint32_t* a, const uint32_t* b) {
    asm volatile(
        "mma.sync.aligned.m16n8k8.row.col.f32.tf32.tf32.f32 "
        "{%0,%1,%2,%3}, {%4,%5,%6,%7}, {%8,%9}, {%0,%1,%2,%3};"
        : "+f"(c[0]), "+f"(c[1]), "+f"(c[2]), "+f"(c[3])
        : "r"(a[0]), "r"(a[1]), "r"(a[2]), "r"(a[3]), "r"(b[0]), "r"(b[1]));
}

__device__ __forceinline__ void mma_bf16(float* c, const uint32_t* a, const uint32_t* b) {
    asm volatile(
        "mma.sync.aligned.m16n8k16.row.col.f32.bf16.bf16.f32 "
        "{%0,%1,%2,%3}, {%4,%5,%6,%7}, {%8,%9}, {%0,%1,%2,%3};"
        : "+f"(c[0]), "+f"(c[1]), "+f"(c[2]), "+f"(c[3])
        : "r"(a[0]), "r"(a[1]), "r"(a[2]), "r"(a[3]), "r"(b[0]), "r"(b[1]));
}

__device__ __forceinline__ void split_pack_bf16(float x0, float x1,
                                                uint32_t& hi, uint32_t& lo) {
    __nv_bfloat162 h = __floats2bfloat162_rn(x0, x1);
    float f0 = __bfloat162float(h.x);
    float f1 = __bfloat162float(h.y);
    __nv_bfloat162 l = __floats2bfloat162_rn(x0 - f0, x1 - f1);
    hi = *(uint32_t*)&h;
    lo = *(uint32_t*)&l;
}

__device__ __forceinline__ void cp16(uint32_t dst, const void* src) {
    asm volatile("cp.async.ca.shared.global [%0], [%1], 16;"
                 :: "r"(dst), "l"(src) : "memory");
}

#define MBARRIER_INIT(addr, count) \
    asm volatile("mbarrier.init.shared.b64 [%0], %1;" :: "r"((uint32_t)(addr)), "r"((uint32_t)(count)) : "memory")
#define MBARRIER_ARRIVE(addr) \
    asm volatile("mbarrier.arrive.shared.b64 _, [%0];" :: "r"((uint32_t)(addr)) : "memory")
#define MBARRIER_WAIT_PARITY(addr, parity) do { \
    uint32_t _m = (uint32_t)(addr); uint32_t _p = (uint32_t)(parity); uint32_t _d; \
    asm volatile("{\n\t.reg .pred p;\n\t" \
        "mbarrier.try_wait.parity.acquire.cta.shared::cta.b64 p, [%1], %2;\n\t" \
        "selp.b32 %0, 1, 0, p;\n\t}" : "=r"(_d) : "r"(_m), "r"(_p) : "memory"); \
    if (!_d) { \
        asm volatile("{\n\t.reg .pred P1;\n\t" \
            "WL_%=:\n\t" \
            "mbarrier.try_wait.parity.acquire.cta.shared::cta.b64 P1, [%0], %1, 0x989680;\n\t" \
            "@P1 bra.uni WD_%=;\n\tbra.uni WL_%=;\n\tWD_%=:\n\t}" \
            :: "r"(_m), "r"(_p) : "memory"); \
    } } while (0)

// ============================================================================
// Prep kernels (R10 proven): split fp32 -> bf16 hi/lo, fragment-major layout.
// ============================================================================
__global__ __launch_bounds__(256) void prep_a(
    const float* __restrict__ A, uint4* __restrict__ H, uint4* __restrict__ L, int K)
{
    const size_t o = (size_t)blockIdx.x * 256 + threadIdx.x;
    const int u4 = (int)(o & 511);
    const int tile = (int)(o >> 9);
    const int kT = K >> 5;
    const int mt = tile / kT, kt = tile % kT;
    const int blkPair = u4 >> 5;
    const int m16 = blkPair >> 1, kblk = blkPair & 1;
    const int rem = u4 & 31;
    const int g = rem >> 2, t4 = rem & 3;
    const int r0 = mt * 128 + m16 * 16 + g;
    const int kb = kt * 32 + kblk * 16 + t4 * 2;
    const float* p0 = A + (size_t)r0 * K + kb;
    const float* p1 = p0 + (size_t)8 * K;
    const float2 a00 = *(const float2*)p0;
    const float2 a10 = *(const float2*)p1;
    const float2 a01 = *(const float2*)(p0 + 8);
    const float2 a11 = *(const float2*)(p1 + 8);
    uint4 hv, lv;
    split_pack_bf16(a00.x, a00.y, hv.x, lv.x);
    split_pack_bf16(a10.x, a10.y, hv.y, lv.y);
    split_pack_bf16(a01.x, a01.y, hv.z, lv.z);
    split_pack_bf16(a11.x, a11.y, hv.w, lv.w);
    H[o] = hv; L[o] = lv;
}

__global__ __launch_bounds__(256) void prep_b(
    const float* __restrict__ B, uint4* __restrict__ H, uint4* __restrict__ L, int K)
{
    const size_t o = (size_t)blockIdx.x * 256 + threadIdx.x;
    const int u4 = (int)(o & 511);
    const int tile = (int)(o >> 9);
    const int kT = K >> 5;
    const int nt = tile / kT, kt = tile % kT;
    const int blkPair = u4 >> 4;
    const int nblk = blkPair >> 1, kblk = blkPair & 1;
    const int rem = u4 & 15;
    const int g = rem >> 1, j = rem & 1;
    const int n = nt * 128 + nblk * 8 + g;
    const int kb = kt * 32 + kblk * 16 + j * 4;
    const float4 p = *(const float4*)(B + (size_t)n * K + kb);
    const float4 q = *(const float4*)(B + (size_t)n * K + kb + 8);
    uint4 hv, lv;
    split_pack_bf16(p.x, p.y, hv.x, lv.x);
    split_pack_bf16(q.x, q.y, hv.y, lv.y);
    split_pack_bf16(p.z, p.w, hv.z, lv.z);
    split_pack_bf16(q.z, q.w, hv.w, lv.w);
    H[o] = hv; L[o] = lv;
}

// ============================================================================
// 3xBF16 tensor-core GEMM on pre-split fragment-major operands (R11 proven).
// ============================================================================
static constexpr int STAGE_E = 16384;
static constexpr int GEMM_SMEM = 3 * STAGE_E * 2;     // 98304 bytes

__global__ __launch_bounds__(256, 2) void gemm_pre(
    const uint4* __restrict__ AH, const uint4* __restrict__ AL,
    const uint4* __restrict__ BH, const uint4* __restrict__ BL,
    const float* __restrict__ bias, float* __restrict__ C,
    int N, int kT, int roundFromTile)
{
    extern __shared__ uint16_t smu[];
    const int tid = threadIdx.x;
    const int wid = tid >> 5;
    const int lane = tid & 31;
    const int g = lane >> 2;
    const int t4 = lane & 3;
    const int wm = wid >> 1;
    const int wn = wid & 1;
    const int mt = blockIdx.y;
    const int nt = blockIdx.x;
    const uint32_t smem_base = (uint32_t)__cvta_generic_to_shared(smu);

    const size_t atile = (size_t)mt * kT;
    const size_t btile = (size_t)nt * kT;

    auto issue = [&](int j, int st) {
        const uint32_t dst0 = smem_base + st * 32768;
#pragma unroll
        for (int s = 0; s < 8; s++) {
            const int arr = s >> 1;
            const int off = tid + (s & 1) * 256;
            const uint4* bp = (arr == 0) ? AH : (arr == 1) ? AL
                             : (arr == 2) ? BH : BL;
            const size_t tb = (arr < 2) ? atile : btile;
            cp16(dst0 + arr * 8192 + off * 16, bp + (tb + j) * 512 + off);
        }
        asm volatile("cp.async.commit_group;" ::: "memory");
    };

    float acc[2][8][4];
#pragma unroll
    for (int mtl = 0; mtl < 2; mtl++)
#pragma unroll
        for (int ntl = 0; ntl < 8; ntl++)
#pragma unroll
            for (int i = 0; i < 4; i++) acc[mtl][ntl][i] = 0.f;

    issue(0, 0);
    issue(1, 1);

    for (int j = 0; j < kT; j++) {
        if (j + 1 < kT) {
            asm volatile("cp.async.wait_group 1;" ::: "memory");
        } else {
            asm volatile("cp.async.wait_group 0;" ::: "memory");
        }
        __syncthreads();
        if (j + 2 < kT) issue(j + 2, (j + 2) % 3);

        const uint16_t* stg = smu + (j % 3) * STAGE_E;
#pragma unroll
        for (int kblk = 0; kblk < 2; kblk++) {
            uint4 ahi[2], alo[2];
#pragma unroll
            for (int mtl = 0; mtl < 2; mtl++) {
                const int mblk = wm * 2 + mtl;
                const int base = (mblk * 2 + kblk) * 256 + g * 32 + t4 * 8;
                ahi[mtl] = *(const uint4*)(stg + base);
                alo[mtl] = *(const uint4*)(stg + 4096 + base);
            }
#pragma unroll
            for (int ntl = 0; ntl < 8; ntl++) {
                const int nblk = wn * 8 + ntl;
                const int bbase = (nblk * 2 + kblk) * 128 + g * 16 + t4 * 4;
                uint2 bh = *(const uint2*)(stg + 8192 + bbase);
                uint2 bl = *(const uint2*)(stg + 12288 + bbase);
#pragma unroll
                for (int mtl = 0; mtl < 2; mtl++) {
                    mma_bf16(acc[mtl][ntl], (const uint32_t*)&ahi[mtl], (const uint32_t*)&bh);
                    mma_bf16(acc[mtl][ntl], (const uint32_t*)&ahi[mtl], (const uint32_t*)&bl);
                    mma_bf16(acc[mtl][ntl], (const uint32_t*)&alo[mtl], (const uint32_t*)&bh);
                }
            }
        }
    }

    const bool roundT = (nt >= roundFromTile);
    const int bm = mt * 128;
    const int bn = nt * 128;
#pragma unroll
    for (int mtl = 0; mtl < 2; mtl++) {
        const int r0 = bm + wm * 32 + mtl * 16 + g;
#pragma unroll
        for (int ntl = 0; ntl < 8; ntl++) {
            const int c0 = bn + wn * 64 + ntl * 8 + t4 * 2;
            const float b0 = bias[c0];
            const float b1 = bias[c0 + 1];
            float2 v0, v1;
            v0.x = acc[mtl][ntl][0] + b0; v0.y = acc[mtl][ntl][1] + b1;
            v1.x = acc[mtl][ntl][2] + b0; v1.y = acc[mtl][ntl][3] + b1;
            if (roundT) {
                v0.x = tf32_rna(v0.x); v0.y = tf32_rna(v0.y);
                v1.x = tf32_rna(v1.x); v1.y = tf32_rna(v1.y);
            }
            *(float2*)(C + (size_t)r0 * N + c0) = v0;
            *(float2*)(C + (size_t)(r0 + 8) * N + c0) = v1;
        }
    }
}

// ============================================================================
// Flash attention (R12 structure, base-2 softmax): tf32 mma.sync,
// producer-warp mbarrier pipeline, 4 fat compute warps x 32 q-rows.
// ============================================================================
static constexpr int ABQ = 128, ABK = 32, APAD = 68, PPAD = 36;
static constexpr int QF0 = 32;
static constexpr int KV0 = QF0 + ABQ * APAD;            // 8736
static constexpr int PF0 = KV0 + 3 * 4352;              // 21792
static constexpr int ATTN_SMEM = (PF0 + 4 * 32 * PPAD) * 4;  // 105600 B

__global__ __launch_bounds__(160, 2) void attn_mma(
    const float* __restrict__ qkv, float* __restrict__ out)
{
    extern __shared__ float sm[];
    const int tid = threadIdx.x;
    const int wid = tid >> 5;
    const int lane = tid & 31;
    const int g = lane >> 2;
    const int t4 = lane & 3;
    const int qi = gridDim.x - 1 - blockIdx.x;
    const int h = blockIdx.y;
    const int b = blockIdx.z;
    const int q0 = qi * ABQ;
    const size_t rs = (size_t)3 * En;
    const float* qbase = qkv + (size_t)b * Sn * rs + (size_t)h * Dn;
    const float* kbase = qbase + En;
    const float* vbase = qbase + 2 * En;
    const uint32_t smem_base = (uint32_t)__cvta_generic_to_shared(sm);
    const int ntiles = 4 * qi + 4;

    if (tid == 0) {
#pragma unroll
        for (int s = 0; s < 3; s++) {
            MBARRIER_INIT(smem_base + s * 8, 32);
            MBARRIER_INIT(smem_base + 24 + s * 8, 4);
        }
    }

    // Q tile -> smem, scale = 0.125 * log2(e) (base-2 softmax), tf32-rna
    if (tid < 128) {
        const float qscale = 0.125f * 1.4426950408889634f;
        for (int i = tid; i < ABQ * 16; i += 128) {
            const int row = i >> 4, c4 = (i & 15) * 4;
            float4 v = *(const float4*)(qbase + (size_t)(q0 + row) * rs + c4);
            float4 hi;
            hi.x = tf32_rna(v.x * qscale);
            hi.y = tf32_rna(v.y * qscale);
            hi.z = tf32_rna(v.z * qscale);
            hi.w = tf32_rna(v.w * qscale);
            *(float4*)&sm[QF0 + row * APAD + c4] = hi;
        }
    }
    __syncthreads();

    if (tid >= 128) {
        // -------- producer warp --------
        for (int j = 0; j < ntiles; j++) {
            const int q3 = j / 3;
            const int s = j - 3 * q3;
            if (j >= 3) {
                MBARRIER_WAIT_PARITY(smem_base + 24 + s * 8, (q3 - 1) & 1);
            }
            const int k0 = j * ABK;
            const int base = KV0 + s * 4352;
#pragma unroll
            for (int c = 0; c < 32; c++) {
                const int i = c * 32 + lane;
                const int isV = i >> 9;
                const int ii = i & 511;
                const int row = ii >> 4, q = ii & 15;
                const float* src = (isV ? vbase : kbase) + (size_t)(k0 + row) * rs + q * 4;
                const int dstf = base + isV * 2176 + row * APAD + q * 4;
                cp16(smem_base + dstf * 4, src);
            }
            asm volatile("cp.async.commit_group;" ::: "memory");
            if (j >= 2) {
                asm volatile("cp.async.wait_group 2;" ::: "memory");
                MBARRIER_ARRIVE(smem_base + ((j - 2) % 3) * 8);
            }
        }
        asm volatile("cp.async.wait_group 1;" ::: "memory");
        MBARRIER_ARRIVE(smem_base + ((ntiles - 2) % 3) * 8);
        asm volatile("cp.async.wait_group 0;" ::: "memory");
        MBARRIER_ARRIVE(smem_base + ((ntiles - 1) % 3) * 8);
        return;
    }

    // -------- compute warps: 32 q-rows each (mt = 2 blocks of 16) --------
    float m_[2][2], l_[2][2];
#pragma unroll
    for (int mt = 0; mt < 2; mt++) {
        m_[mt][0] = -1e30f; m_[mt][1] = -1e30f;
        l_[mt][0] = 0.f;    l_[mt][1] = 0.f;
    }
    float o[2][8][4];
#pragma unroll
    for (int mt = 0; mt < 2; mt++)
#pragma unroll
        for (int nt = 0; nt < 8; nt++)
#pragma unroll
            for (int i = 0; i < 4; i++) o[mt][nt][i] = 0.f;

    const int wrow = wid * 32;
    float* Pw = sm + PF0 + wid * (32 * PPAD);

    for (int jt = 0; jt < ntiles; jt++) {
        const int q3 = jt / 3;
        const int s = jt - 3 * q3;
        const int k0 = jt * ABK;
        MBARRIER_WAIT_PARITY(smem_base + s * 8, q3 & 1);

        const float* Kb = sm + KV0 + s * 4352;
        const float* Vb = Kb + 2176;

        // ---- S = (Q*qscale) @ K^T ----
        float acc[2][4][4];
#pragma unroll
        for (int mt = 0; mt < 2; mt++)
#pragma unroll
            for (int nt = 0; nt < 4; nt++)
#pragma unroll
                for (int i = 0; i < 4; i++) acc[mt][nt][i] = 0.f;

#pragma unroll
        for (int kb = 0; kb < 8; kb++) {
            uint32_t aq[2][4];
#pragma unroll
            for (int mt = 0; mt < 2; mt++) {
                const int r = wrow + mt * 16 + g;
                aq[mt][0] = __float_as_uint(sm[QF0 + r * APAD + kb * 8 + t4]);
                aq[mt][1] = __float_as_uint(sm[QF0 + (r + 8) * APAD + kb * 8 + t4]);
                aq[mt][2] = __float_as_uint(sm[QF0 + r * APAD + kb * 8 + t4 + 4]);
                aq[mt][3] = __float_as_uint(sm[QF0 + (r + 8) * APAD + kb * 8 + t4 + 4]);
            }
#pragma unroll
            for (int nt = 0; nt < 4; nt++) {
                uint32_t bh[2];
                bh[0] = __float_as_uint(Kb[(nt * 8 + g) * APAD + kb * 8 + t4]);
                bh[1] = __float_as_uint(Kb[(nt * 8 + g) * APAD + kb * 8 + t4 + 4]);
#pragma unroll
                for (int mt = 0; mt < 2; mt++)
                    mma_tf32(acc[mt][nt], aq[mt], bh);
            }
        }

        // ---- causal mask (4 diagonal-overlapping tiles) ----
        if (jt >= ntiles - 4) {
#pragma unroll
            for (int mt = 0; mt < 2; mt++) {
                const int r0g = q0 + wrow + mt * 16 + g;
                const int r1g = r0g + 8;
#pragma unroll
                for (int nt = 0; nt < 4; nt++) {
                    const int c = k0 + nt * 8 + t4 * 2;
                    if (c > r0g)     acc[mt][nt][0] = -1e30f;
                    if (c + 1 > r0g) acc[mt][nt][1] = -1e30f;
                    if (c > r1g)     acc[mt][nt][2] = -1e30f;
                    if (c + 1 > r1g) acc[mt][nt][3] = -1e30f;
                }
            }
        }

        // ---- online softmax (base-2) ----
        float al[2][2];
#pragma unroll
        for (int mt = 0; mt < 2; mt++) {
            float mx0 = -1e30f, mx1 = -1e30f;
#pragma unroll
            for (int nt = 0; nt < 4; nt++) {
                mx0 = fmaxf(mx0, fmaxf(acc[mt][nt][0], acc[mt][nt][1]));
                mx1 = fmaxf(mx1, fmaxf(acc[mt][nt][2], acc[mt][nt][3]));
            }
            mx0 = fmaxf(mx0, __shfl_xor_sync(0xffffffffu, mx0, 1));
            mx0 = fmaxf(mx0, __shfl_xor_sync(0xffffffffu, mx0, 2));
            mx1 = fmaxf(mx1, __shfl_xor_sync(0xffffffffu, mx1, 1));
            mx1 = fmaxf(mx1, __shfl_xor_sync(0xffffffffu, mx1, 2));
            const float mn0 = fmaxf(m_[mt][0], mx0);
            const float mn1 = fmaxf(m_[mt][1], mx1);
            const float a0 = ex2(m_[mt][0] - mn0);
            const float a1 = ex2(m_[mt][1] - mn1);
            m_[mt][0] = mn0; m_[mt][1] = mn1;
            float s0 = 0.f, s1 = 0.f;
#pragma unroll
            for (int nt = 0; nt < 4; nt++) {
                acc[mt][nt][0] = ex2(acc[mt][nt][0] - mn0); s0 += acc[mt][nt][0];
                acc[mt][nt][1] = ex2(acc[mt][nt][1] - mn0); s0 += acc[mt][nt][1];
                acc[mt][nt][2] = ex2(acc[mt][nt][2] - mn1); s1 += acc[mt][nt][2];
                acc[mt][nt][3] = ex2(acc[mt][nt][3] - mn1); s1 += acc[mt][nt][3];
            }
            s0 += __shfl_xor_sync(0xffffffffu, s0, 1);
            s0 += __shfl_xor_sync(0xffffffffu, s0, 2);
            s1 += __shfl_xor_sync(0xffffffffu, s1, 1);
            s1 += __shfl_xor_sync(0xffffffffu, s1, 2);
            l_[mt][0] = l_[mt][0] * a0 + s0;
            l_[mt][1] = l_[mt][1] * a1 + s1;
            al[mt][0] = a0; al[mt][1] = a1;
        }

        // ---- P -> warp-private smem ----
#pragma unroll
        for (int mt = 0; mt < 2; mt++) {
            const int rb = mt * 16;
#pragma unroll
            for (int nt = 0; nt < 4; nt++) {
                Pw[(rb + g) * PPAD + nt * 8 + t4 * 2]           = tf32_rna(acc[mt][nt][0]);
                Pw[(rb + g) * PPAD + nt * 8 + t4 * 2 + 1]       = tf32_rna(acc[mt][nt][1]);
                Pw[(rb + g + 8) * PPAD + nt * 8 + t4 * 2]       = tf32_rna(acc[mt][nt][2]);
                Pw[(rb + g + 8) * PPAD + nt * 8 + t4 * 2 + 1]   = tf32_rna(acc[mt][nt][3]);
            }
        }
        __syncwarp();

        // ---- rescale O ----
#pragma unroll
        for (int mt = 0; mt < 2; mt++)
#pragma unroll
            for (int nt = 0; nt < 8; nt++) {
                o[mt][nt][0] *= al[mt][0]; o[mt][nt][1] *= al[mt][0];
                o[mt][nt][2] *= al[mt][1]; o[mt][nt][3] *= al[mt][1];
            }

        // ---- O += P @ V ----
#pragma unroll
        for (int kb = 0; kb < 4; kb++) {
            uint32_t ap[2][4];
#pragma unroll
            for (int mt = 0; mt < 2; mt++) {
                const int rb = mt * 16;
                ap[mt][0] = __float_as_uint(Pw[(rb + g) * PPAD + kb * 8 + t4]);
                ap[mt][1] = __float_as_uint(Pw[(rb + g + 8) * PPAD + kb * 8 + t4]);
                ap[mt][2] = __float_as_uint(Pw[(rb + g) * PPAD + kb * 8 + t4 + 4]);
                ap[mt][3] = __float_as_uint(Pw[(rb + g + 8) * PPAD + kb * 8 + t4 + 4]);
            }
#pragma unroll
            for (int nt = 0; nt < 8; nt++) {
                uint32_t bh[2];
                bh[0] = __float_as_uint(Vb[(kb * 8 + t4) * APAD + nt * 8 + g]);
                bh[1] = __float_as_uint(Vb[(kb * 8 + t4 + 4) * APAD + nt * 8 + g]);
#pragma unroll
                for (int mt = 0; mt < 2; mt++)
                    mma_tf32(o[mt][nt], ap[mt], bh);
            }
        }
        __syncwarp();
        if (lane == 0) MBARRIER_ARRIVE(smem_base + 24 + s * 8);
    }

    // ---- normalize + store (coalesced float2 rows) ----
#pragma unroll
    for (int mt = 0; mt < 2; mt++) {
        const float i0 = 1.f / l_[mt][0];
        const float i1 = 1.f / l_[mt][1];
        const int r0g = q0 + wrow + mt * 16 + g;
#pragma unroll
        for (int nt = 0; nt < 8; nt++) {
            const int col = h * Dn + nt * 8 + t4 * 2;
            float2 v0, v1;
            v0.x = o[mt][nt][0] * i0; v0.y = o[mt][nt][1] * i0;
            v1.x = o[mt][nt][2] * i1; v1.y = o[mt][nt][3] * i1;
            *(float2*)(out + ((size_t)b * Sn + r0g) * En + col) = v0;
            *(float2*)(out + ((size_t)b * Sn + r0g + 8) * En + col) = v1;
        }
    }
}

// ----------------------------------------------------------------------------
extern "C" void kernel_launch(void* const* d_in, const int* in_sizes, int n_in,
                              void* d_out, int out_size)
{
    const float* x     = (const float*)d_in[0];
    const float* w_in  = (const float*)d_in[1];
    const float* b_in  = (const float*)d_in[2];
    const float* w_out = (const float*)d_in[3];
    const float* b_out = (const float*)d_in[4];
    float* out = (float*)d_out;

    float *qkv, *attn;
    uint4 *xh, *xl, *ah, *al, *wih, *wil, *woh, *wol;
    cudaGetSymbolAddress((void**)&qkv, g_qkv);
    cudaGetSymbolAddress((void**)&attn, g_attn);
    cudaGetSymbolAddress((void**)&xh, g_xh);
    cudaGetSymbolAddress((void**)&xl, g_xl);
    cudaGetSymbolAddress((void**)&ah, g_ah);
    cudaGetSymbolAddress((void**)&al, g_al);
    cudaGetSymbolAddress((void**)&wih, g_wih);
    cudaGetSymbolAddress((void**)&wil, g_wil);
    cudaGetSymbolAddress((void**)&woh, g_woh);
    cudaGetSymbolAddress((void**)&wol, g_wol);

    static bool attr_set = false;
    if (!attr_set) {
        cudaFuncSetAttribute(gemm_pre, cudaFuncAttributeMaxDynamicSharedMemorySize,
                             GEMM_SMEM);
        cudaFuncSetAttribute(attn_mma, cudaFuncAttributeMaxDynamicSharedMemorySize,
                             ATTN_SMEM);
        attr_set = true;
    }

    // 0) Pre-split operands into fragment-major bf16 hi/lo
    prep_a<<<4096, 256>>>(x, xh, xl, En);
    prep_b<<<1536, 256>>>(w_in, wih, wil, En);

    // 1) QKV projection; K/V columns (tiles >= 8) pre-rounded to tf32
    {
        dim3 grid(24, 64);
        gemm_pre<<<grid, 256, GEMM_SMEM>>>(xh, xl, wih, wil, b_in, qkv,
                                           3 * En, En / 32, 8);
    }

    // 2) Causal flash attention (tf32, base-2 softmax, producer pipeline)
    {
        dim3 grid(Sn / ABQ, Hn, Bn);
        attn_mma<<<grid, 160, ATTN_SMEM>>>(qkv, attn);
    }

    // 3) Output projection
    prep_a<<<4096, 256>>>(attn, ah, al, En);
    prep_b<<<512, 256>>>(w_out, woh, wol, En);
    {
        dim3 grid(8, 64);
        gemm_pre<<<grid, 256, GEMM_SMEM>>>(ah, al, woh, wol, b_out, out,
                                           En, En / 32, 1 << 30);
    }
}

// round 15
// speedup vs baseline: 1.5305x; 1.0089x over previous
#include <cuda_runtime.h>
#include <cuda_bf16.h>
#include <cstdint>
#include <cstddef>

// Problem constants
static constexpr int Bn = 4;
static constexpr int Sn = 2048;
static constexpr int En = 1024;
static constexpr int Hn = 16;
static constexpr int Dn = 64;

// Scratch (device globals; no cudaMalloc allowed)
__device__ float g_qkv[(size_t)Bn * Sn * 3 * En];   // [B,S,3E]
__device__ float g_attn[(size_t)Bn * Sn * En];      // [B,S,E]

// Pre-split bf16 hi/lo operand tiles (fragment-major layout)
__device__ uint4 g_xh[1048576], g_xl[1048576];      // x
__device__ uint4 g_ah[1048576], g_al[1048576];      // attn
__device__ uint4 g_wih[393216], g_wil[393216];      // w_in
__device__ uint4 g_woh[131072], g_wol[131072];      // w_out

__device__ __forceinline__ float tf32_rna(float x) {
    uint32_t u;
    asm("cvt.rna.tf32.f32 %0, %1;" : "=r"(u) : "f"(x));
    return __uint_as_float(u);
}

__device__ __forceinline__ float ex2(float x) {
    float y;
    asm("ex2.approx.ftz.f32 %0, %1;" : "=f"(y) : "f"(x));
    return y;
}

__device__ __forceinline__ void mma_tf32(float* c, const uint32_t* a, const uint32_t* b) {
    asm volatile(
        "mma.sync.aligned.m16n8k8.row.col.f32.tf32.tf32.f32 "
        "{%0,%1,%2,%3}, {%4,%5,%6,%7}, {%8,%9}, {%0,%1,%2,%3};"
        : "+f"(c[0]), "+f"(c[1]), "+f"(c[2]), "+f"(c[3])
        : "r"(a[0]), "r"(a[1]), "r"(a[2]), "r"(a[3]), "r"(b[0]), "r"(b[1]));
}

__device__ __forceinline__ void mma_bf16(float* c, const uint32_t* a, const uint32_t* b) {
    asm volatile(
        "mma.sync.aligned.m16n8k16.row.col.f32.bf16.bf16.f32 "
        "{%0,%1,%2,%3}, {%4,%5,%6,%7}, {%8,%9}, {%0,%1,%2,%3};"
        : "+f"(c[0]), "+f"(c[1]), "+f"(c[2]), "+f"(c[3])
        : "r"(a[0]), "r"(a[1]), "r"(a[2]), "r"(a[3]), "r"(b[0]), "r"(b[1]));
}

__device__ __forceinline__ void split_pack_bf16(float x0, float x1,
                                                uint32_t& hi, uint32_t& lo) {
    __nv_bfloat162 h = __floats2bfloat162_rn(x0, x1);
    float f0 = __bfloat162float(h.x);
    float f1 = __bfloat162float(h.y);
    __nv_bfloat162 l = __floats2bfloat162_rn(x0 - f0, x1 - f1);
    hi = *(uint32_t*)&h;
    lo = *(uint32_t*)&l;
}

__device__ __forceinline__ void cp16(uint32_t dst, const void* src) {
    asm volatile("cp.async.ca.shared.global [%0], [%1], 16;"
                 :: "r"(dst), "l"(src) : "memory");
}

#define MBARRIER_INIT(addr, count) \
    asm volatile("mbarrier.init.shared.b64 [%0], %1;" :: "r"((uint32_t)(addr)), "r"((uint32_t)(count)) : "memory")
#define MBARRIER_ARRIVE(addr) \
    asm volatile("mbarrier.arrive.shared.b64 _, [%0];" :: "r"((uint32_t)(addr)) : "memory")
#define MBARRIER_WAIT_PARITY(addr, parity) do { \
    uint32_t _m = (uint32_t)(addr); uint32_t _p = (uint32_t)(parity); uint32_t _d; \
    asm volatile("{\n\t.reg .pred p;\n\t" \
        "mbarrier.try_wait.parity.acquire.cta.shared::cta.b64 p, [%1], %2;\n\t" \
        "selp.b32 %0, 1, 0, p;\n\t}" : "=r"(_d) : "r"(_m), "r"(_p) : "memory"); \
    if (!_d) { \
        asm volatile("{\n\t.reg .pred P1;\n\t" \
            "WL_%=:\n\t" \
            "mbarrier.try_wait.parity.acquire.cta.shared::cta.b64 P1, [%0], %1, 0x989680;\n\t" \
            "@P1 bra.uni WD_%=;\n\tbra.uni WL_%=;\n\tWD_%=:\n\t}" \
            :: "r"(_m), "r"(_p) : "memory"); \
    } } while (0)

// ============================================================================
// Prep kernels (R10 proven): split fp32 -> bf16 hi/lo, fragment-major layout.
// ============================================================================
__global__ __launch_bounds__(256) void prep_a(
    const float* __restrict__ A, uint4* __restrict__ H, uint4* __restrict__ L, int K)
{
    const size_t o = (size_t)blockIdx.x * 256 + threadIdx.x;
    const int u4 = (int)(o & 511);
    const int tile = (int)(o >> 9);
    const int kT = K >> 5;
    const int mt = tile / kT, kt = tile % kT;
    const int blkPair = u4 >> 5;
    const int m16 = blkPair >> 1, kblk = blkPair & 1;
    const int rem = u4 & 31;
    const int g = rem >> 2, t4 = rem & 3;
    const int r0 = mt * 128 + m16 * 16 + g;
    const int kb = kt * 32 + kblk * 16 + t4 * 2;
    const float* p0 = A + (size_t)r0 * K + kb;
    const float* p1 = p0 + (size_t)8 * K;
    const float2 a00 = *(const float2*)p0;
    const float2 a10 = *(const float2*)p1;
    const float2 a01 = *(const float2*)(p0 + 8);
    const float2 a11 = *(const float2*)(p1 + 8);
    uint4 hv, lv;
    split_pack_bf16(a00.x, a00.y, hv.x, lv.x);
    split_pack_bf16(a10.x, a10.y, hv.y, lv.y);
    split_pack_bf16(a01.x, a01.y, hv.z, lv.z);
    split_pack_bf16(a11.x, a11.y, hv.w, lv.w);
    H[o] = hv; L[o] = lv;
}

__global__ __launch_bounds__(256) void prep_b(
    const float* __restrict__ B, uint4* __restrict__ H, uint4* __restrict__ L, int K)
{
    const size_t o = (size_t)blockIdx.x * 256 + threadIdx.x;
    const int u4 = (int)(o & 511);
    const int tile = (int)(o >> 9);
    const int kT = K >> 5;
    const int nt = tile / kT, kt = tile % kT;
    const int blkPair = u4 >> 4;
    const int nblk = blkPair >> 1, kblk = blkPair & 1;
    const int rem = u4 & 15;
    const int g = rem >> 1, j = rem & 1;
    const int n = nt * 128 + nblk * 8 + g;
    const int kb = kt * 32 + kblk * 16 + j * 4;
    const float4 p = *(const float4*)(B + (size_t)n * K + kb);
    const float4 q = *(const float4*)(B + (size_t)n * K + kb + 8);
    uint4 hv, lv;
    split_pack_bf16(p.x, p.y, hv.x, lv.x);
    split_pack_bf16(q.x, q.y, hv.y, lv.y);
    split_pack_bf16(p.z, p.w, hv.z, lv.z);
    split_pack_bf16(q.z, q.w, hv.w, lv.w);
    H[o] = hv; L[o] = lv;
}

// ============================================================================
// 3xBF16 tensor-core GEMM on pre-split fragment-major operands (R11 proven).
// ============================================================================
static constexpr int STAGE_E = 16384;
static constexpr int GEMM_SMEM = 3 * STAGE_E * 2;     // 98304 bytes

__global__ __launch_bounds__(256, 2) void gemm_pre(
    const uint4* __restrict__ AH, const uint4* __restrict__ AL,
    const uint4* __restrict__ BH, const uint4* __restrict__ BL,
    const float* __restrict__ bias, float* __restrict__ C,
    int N, int kT, int roundFromTile)
{
    extern __shared__ uint16_t smu[];
    const int tid = threadIdx.x;
    const int wid = tid >> 5;
    const int lane = tid & 31;
    const int g = lane >> 2;
    const int t4 = lane & 3;
    const int wm = wid >> 1;
    const int wn = wid & 1;
    const int mt = blockIdx.y;
    const int nt = blockIdx.x;
    const uint32_t smem_base = (uint32_t)__cvta_generic_to_shared(smu);

    const size_t atile = (size_t)mt * kT;
    const size_t btile = (size_t)nt * kT;

    auto issue = [&](int j, int st) {
        const uint32_t dst0 = smem_base + st * 32768;
#pragma unroll
        for (int s = 0; s < 8; s++) {
            const int arr = s >> 1;
            const int off = tid + (s & 1) * 256;
            const uint4* bp = (arr == 0) ? AH : (arr == 1) ? AL
                             : (arr == 2) ? BH : BL;
            const size_t tb = (arr < 2) ? atile : btile;
            cp16(dst0 + arr * 8192 + off * 16, bp + (tb + j) * 512 + off);
        }
        asm volatile("cp.async.commit_group;" ::: "memory");
    };

    float acc[2][8][4];
#pragma unroll
    for (int mtl = 0; mtl < 2; mtl++)
#pragma unroll
        for (int ntl = 0; ntl < 8; ntl++)
#pragma unroll
            for (int i = 0; i < 4; i++) acc[mtl][ntl][i] = 0.f;

    issue(0, 0);
    issue(1, 1);

    for (int j = 0; j < kT; j++) {
        if (j + 1 < kT) {
            asm volatile("cp.async.wait_group 1;" ::: "memory");
        } else {
            asm volatile("cp.async.wait_group 0;" ::: "memory");
        }
        __syncthreads();
        if (j + 2 < kT) issue(j + 2, (j + 2) % 3);

        const uint16_t* stg = smu + (j % 3) * STAGE_E;
#pragma unroll
        for (int kblk = 0; kblk < 2; kblk++) {
            uint4 ahi[2], alo[2];
#pragma unroll
            for (int mtl = 0; mtl < 2; mtl++) {
                const int mblk = wm * 2 + mtl;
                const int base = (mblk * 2 + kblk) * 256 + g * 32 + t4 * 8;
                ahi[mtl] = *(const uint4*)(stg + base);
                alo[mtl] = *(const uint4*)(stg + 4096 + base);
            }
#pragma unroll
            for (int ntl = 0; ntl < 8; ntl++) {
                const int nblk = wn * 8 + ntl;
                const int bbase = (nblk * 2 + kblk) * 128 + g * 16 + t4 * 4;
                uint2 bh = *(const uint2*)(stg + 8192 + bbase);
                uint2 bl = *(const uint2*)(stg + 12288 + bbase);
#pragma unroll
                for (int mtl = 0; mtl < 2; mtl++) {
                    mma_bf16(acc[mtl][ntl], (const uint32_t*)&ahi[mtl], (const uint32_t*)&bh);
                    mma_bf16(acc[mtl][ntl], (const uint32_t*)&ahi[mtl], (const uint32_t*)&bl);
                    mma_bf16(acc[mtl][ntl], (const uint32_t*)&alo[mtl], (const uint32_t*)&bh);
                }
            }
        }
    }

    const bool roundT = (nt >= roundFromTile);
    const int bm = mt * 128;
    const int bn = nt * 128;
#pragma unroll
    for (int mtl = 0; mtl < 2; mtl++) {
        const int r0 = bm + wm * 32 + mtl * 16 + g;
#pragma unroll
        for (int ntl = 0; ntl < 8; ntl++) {
            const int c0 = bn + wn * 64 + ntl * 8 + t4 * 2;
            const float b0 = bias[c0];
            const float b1 = bias[c0 + 1];
            float2 v0, v1;
            v0.x = acc[mtl][ntl][0] + b0; v0.y = acc[mtl][ntl][1] + b1;
            v1.x = acc[mtl][ntl][2] + b0; v1.y = acc[mtl][ntl][3] + b1;
            if (roundT) {
                v0.x = tf32_rna(v0.x); v0.y = tf32_rna(v0.y);
                v1.x = tf32_rna(v1.x); v1.y = tf32_rna(v1.y);
            }
            *(float2*)(C + (size_t)r0 * N + c0) = v0;
            *(float2*)(C + (size_t)(r0 + 8) * N + c0) = v1;
        }
    }
}

// ============================================================================
// Flash attention (R14 base): tf32 mma.sync, producer pipeline, base-2 softmax.
// NEW (single change): Q stored fragment-major -> 2 LDS.128 per kb instead of
// 8 scalar LDS. Written once per CTA, read every tile.
// QF[((w*2+mt)*8+kb)*128 + (g*4+t4)*4 + comp], comp = hi8 + 2*(ci>>2).
// ============================================================================
static constexpr int ABQ = 128, ABK = 32, APAD = 68, PPAD = 36;
static constexpr int QF0 = 32;
static constexpr int KV0 = QF0 + 8192;                  // Q frag: 8192 floats
static constexpr int PF0 = KV0 + 3 * 4352;              // 21280
static constexpr int ATTN_SMEM = (PF0 + 4 * 32 * PPAD) * 4;  // 103552 B

__global__ __launch_bounds__(160, 2) void attn_mma(
    const float* __restrict__ qkv, float* __restrict__ out)
{
    extern __shared__ float sm[];
    const int tid = threadIdx.x;
    const int wid = tid >> 5;
    const int lane = tid & 31;
    const int g = lane >> 2;
    const int t4 = lane & 3;
    const int qi = gridDim.x - 1 - blockIdx.x;
    const int h = blockIdx.y;
    const int b = blockIdx.z;
    const int q0 = qi * ABQ;
    const size_t rs = (size_t)3 * En;
    const float* qbase = qkv + (size_t)b * Sn * rs + (size_t)h * Dn;
    const float* kbase = qbase + En;
    const float* vbase = qbase + 2 * En;
    const uint32_t smem_base = (uint32_t)__cvta_generic_to_shared(sm);
    const int ntiles = 4 * qi + 4;

    if (tid == 0) {
#pragma unroll
        for (int s = 0; s < 3; s++) {
            MBARRIER_INIT(smem_base + s * 8, 32);
            MBARRIER_INIT(smem_base + 24 + s * 8, 4);
        }
    }

    // Q tile -> fragment-major smem (one-time scatter; amortized over tiles)
    if (tid < 128) {
        const float qscale = 0.125f * 1.4426950408889634f;
        for (int i = tid; i < ABQ * 16; i += 128) {
            const int row = i >> 4, c4 = (i & 15) * 4;
            float4 v = *(const float4*)(qbase + (size_t)(q0 + row) * rs + c4);
            float val[4];
            val[0] = tf32_rna(v.x * qscale);
            val[1] = tf32_rna(v.y * qscale);
            val[2] = tf32_rna(v.z * qscale);
            val[3] = tf32_rna(v.w * qscale);
            const int w = row >> 5, mt = (row >> 4) & 1;
            const int r16 = row & 15, gq = r16 & 7, hi8 = r16 >> 3;
#pragma unroll
            for (int e = 0; e < 4; e++) {
                const int c = c4 + e;
                const int kb = c >> 3, ci = c & 7;
                const int comp = hi8 + 2 * (ci >> 2);
                sm[QF0 + (((w * 2 + mt) * 8 + kb) * 128
                          + (gq * 4 + (ci & 3)) * 4 + comp)] = val[e];
            }
        }
    }
    __syncthreads();

    if (tid >= 128) {
        // -------- producer warp --------
        for (int j = 0; j < ntiles; j++) {
            const int q3 = j / 3;
            const int s = j - 3 * q3;
            if (j >= 3) {
                MBARRIER_WAIT_PARITY(smem_base + 24 + s * 8, (q3 - 1) & 1);
            }
            const int k0 = j * ABK;
            const int base = KV0 + s * 4352;
#pragma unroll
            for (int c = 0; c < 32; c++) {
                const int i = c * 32 + lane;
                const int isV = i >> 9;
                const int ii = i & 511;
                const int row = ii >> 4, q = ii & 15;
                const float* src = (isV ? vbase : kbase) + (size_t)(k0 + row) * rs + q * 4;
                const int dstf = base + isV * 2176 + row * APAD + q * 4;
                cp16(smem_base + dstf * 4, src);
            }
            asm volatile("cp.async.commit_group;" ::: "memory");
            if (j >= 2) {
                asm volatile("cp.async.wait_group 2;" ::: "memory");
                MBARRIER_ARRIVE(smem_base + ((j - 2) % 3) * 8);
            }
        }
        asm volatile("cp.async.wait_group 1;" ::: "memory");
        MBARRIER_ARRIVE(smem_base + ((ntiles - 2) % 3) * 8);
        asm volatile("cp.async.wait_group 0;" ::: "memory");
        MBARRIER_ARRIVE(smem_base + ((ntiles - 1) % 3) * 8);
        return;
    }

    // -------- compute warps: 32 q-rows each (mt = 2 blocks of 16) --------
    float m_[2][2], l_[2][2];
#pragma unroll
    for (int mt = 0; mt < 2; mt++) {
        m_[mt][0] = -1e30f; m_[mt][1] = -1e30f;
        l_[mt][0] = 0.f;    l_[mt][1] = 0.f;
    }
    float o[2][8][4];
#pragma unroll
    for (int mt = 0; mt < 2; mt++)
#pragma unroll
        for (int nt = 0; nt < 8; nt++)
#pragma unroll
            for (int i = 0; i < 4; i++) o[mt][nt][i] = 0.f;

    const int wrow = wid * 32;
    float* Pw = sm + PF0 + wid * (32 * PPAD);
    const float* Qw = sm + QF0 + wid * 2048;   // this warp's Q fragments

    for (int jt = 0; jt < ntiles; jt++) {
        const int q3 = jt / 3;
        const int s = jt - 3 * q3;
        const int k0 = jt * ABK;
        MBARRIER_WAIT_PARITY(smem_base + s * 8, q3 & 1);

        const float* Kb = sm + KV0 + s * 4352;
        const float* Vb = Kb + 2176;

        // ---- S = (Q*qscale) @ K^T (Q fragments via LDS.128) ----
        float acc[2][4][4];
#pragma unroll
        for (int mt = 0; mt < 2; mt++)
#pragma unroll
            for (int nt = 0; nt < 4; nt++)
#pragma unroll
                for (int i = 0; i < 4; i++) acc[mt][nt][i] = 0.f;

#pragma unroll
        for (int kb = 0; kb < 8; kb++) {
            uint4 aq[2];
            aq[0] = *(const uint4*)&Qw[(0 * 8 + kb) * 128 + lane * 4];
            aq[1] = *(const uint4*)&Qw[(1 * 8 + kb) * 128 + lane * 4];
#pragma unroll
            for (int nt = 0; nt < 4; nt++) {
                uint32_t bh[2];
                bh[0] = __float_as_uint(Kb[(nt * 8 + g) * APAD + kb * 8 + t4]);
                bh[1] = __float_as_uint(Kb[(nt * 8 + g) * APAD + kb * 8 + t4 + 4]);
#pragma unroll
                for (int mt = 0; mt < 2; mt++)
                    mma_tf32(acc[mt][nt], (const uint32_t*)&aq[mt], bh);
            }
        }

        // ---- causal mask (4 diagonal-overlapping tiles) ----
        if (jt >= ntiles - 4) {
#pragma unroll
            for (int mt = 0; mt < 2; mt++) {
                const int r0g = q0 + wrow + mt * 16 + g;
                const int r1g = r0g + 8;
#pragma unroll
                for (int nt = 0; nt < 4; nt++) {
                    const int c = k0 + nt * 8 + t4 * 2;
                    if (c > r0g)     acc[mt][nt][0] = -1e30f;
                    if (c + 1 > r0g) acc[mt][nt][1] = -1e30f;
                    if (c > r1g)     acc[mt][nt][2] = -1e30f;
                    if (c + 1 > r1g) acc[mt][nt][3] = -1e30f;
                }
            }
        }

        // ---- online softmax (base-2) ----
        float al[2][2];
#pragma unroll
        for (int mt = 0; mt < 2; mt++) {
            float mx0 = -1e30f, mx1 = -1e30f;
#pragma unroll
            for (int nt = 0; nt < 4; nt++) {
                mx0 = fmaxf(mx0, fmaxf(acc[mt][nt][0], acc[mt][nt][1]));
                mx1 = fmaxf(mx1, fmaxf(acc[mt][nt][2], acc[mt][nt][3]));
            }
            mx0 = fmaxf(mx0, __shfl_xor_sync(0xffffffffu, mx0, 1));
            mx0 = fmaxf(mx0, __shfl_xor_sync(0xffffffffu, mx0, 2));
            mx1 = fmaxf(mx1, __shfl_xor_sync(0xffffffffu, mx1, 1));
            mx1 = fmaxf(mx1, __shfl_xor_sync(0xffffffffu, mx1, 2));
            const float mn0 = fmaxf(m_[mt][0], mx0);
            const float mn1 = fmaxf(m_[mt][1], mx1);
            const float a0 = ex2(m_[mt][0] - mn0);
            const float a1 = ex2(m_[mt][1] - mn1);
            m_[mt][0] = mn0; m_[mt][1] = mn1;
            float s0 = 0.f, s1 = 0.f;
#pragma unroll
            for (int nt = 0; nt < 4; nt++) {
                acc[mt][nt][0] = ex2(acc[mt][nt][0] - mn0); s0 += acc[mt][nt][0];
                acc[mt][nt][1] = ex2(acc[mt][nt][1] - mn0); s0 += acc[mt][nt][1];
                acc[mt][nt][2] = ex2(acc[mt][nt][2] - mn1); s1 += acc[mt][nt][2];
                acc[mt][nt][3] = ex2(acc[mt][nt][3] - mn1); s1 += acc[mt][nt][3];
            }
            s0 += __shfl_xor_sync(0xffffffffu, s0, 1);
            s0 += __shfl_xor_sync(0xffffffffu, s0, 2);
            s1 += __shfl_xor_sync(0xffffffffu, s1, 1);
            s1 += __shfl_xor_sync(0xffffffffu, s1, 2);
            l_[mt][0] = l_[mt][0] * a0 + s0;
            l_[mt][1] = l_[mt][1] * a1 + s1;
            al[mt][0] = a0; al[mt][1] = a1;
        }

        // ---- P -> warp-private smem ----
#pragma unroll
        for (int mt = 0; mt < 2; mt++) {
            const int rb = mt * 16;
#pragma unroll
            for (int nt = 0; nt < 4; nt++) {
                Pw[(rb + g) * PPAD + nt * 8 + t4 * 2]           = tf32_rna(acc[mt][nt][0]);
                Pw[(rb + g) * PPAD + nt * 8 + t4 * 2 + 1]       = tf32_rna(acc[mt][nt][1]);
                Pw[(rb + g + 8) * PPAD + nt * 8 + t4 * 2]       = tf32_rna(acc[mt][nt][2]);
                Pw[(rb + g + 8) * PPAD + nt * 8 + t4 * 2 + 1]   = tf32_rna(acc[mt][nt][3]);
            }
        }
        __syncwarp();

        // ---- rescale O ----
#pragma unroll
        for (int mt = 0; mt < 2; mt++)
#pragma unroll
            for (int nt = 0; nt < 8; nt++) {
                o[mt][nt][0] *= al[mt][0]; o[mt][nt][1] *= al[mt][0];
                o[mt][nt][2] *= al[mt][1]; o[mt][nt][3] *= al[mt][1];
            }

        // ---- O += P @ V ----
#pragma unroll
        for (int kb = 0; kb < 4; kb++) {
            uint32_t ap[2][4];
#pragma unroll
            for (int mt = 0; mt < 2; mt++) {
                const int rb = mt * 16;
                ap[mt][0] = __float_as_uint(Pw[(rb + g) * PPAD + kb * 8 + t4]);
                ap[mt][1] = __float_as_uint(Pw[(rb + g + 8) * PPAD + kb * 8 + t4]);
                ap[mt][2] = __float_as_uint(Pw[(rb + g) * PPAD + kb * 8 + t4 + 4]);
                ap[mt][3] = __float_as_uint(Pw[(rb + g + 8) * PPAD + kb * 8 + t4 + 4]);
            }
#pragma unroll
            for (int nt = 0; nt < 8; nt++) {
                uint32_t bh[2];
                bh[0] = __float_as_uint(Vb[(kb * 8 + t4) * APAD + nt * 8 + g]);
                bh[1] = __float_as_uint(Vb[(kb * 8 + t4 + 4) * APAD + nt * 8 + g]);
#pragma unroll
                for (int mt = 0; mt < 2; mt++)
                    mma_tf32(o[mt][nt], ap[mt], bh);
            }
        }
        __syncwarp();
        if (lane == 0) MBARRIER_ARRIVE(smem_base + 24 + s * 8);
    }

    // ---- normalize + store (coalesced float2 rows) ----
#pragma unroll
    for (int mt = 0; mt < 2; mt++) {
        const float i0 = 1.f / l_[mt][0];
        const float i1 = 1.f / l_[mt][1];
        const int r0g = q0 + wrow + mt * 16 + g;
#pragma unroll
        for (int nt = 0; nt < 8; nt++) {
            const int col = h * Dn + nt * 8 + t4 * 2;
            float2 v0, v1;
            v0.x = o[mt][nt][0] * i0; v0.y = o[mt][nt][1] * i0;
            v1.x = o[mt][nt][2] * i1; v1.y = o[mt][nt][3] * i1;
            *(float2*)(out + ((size_t)b * Sn + r0g) * En + col) = v0;
            *(float2*)(out + ((size_t)b * Sn + r0g + 8) * En + col) = v1;
        }
    }
}

// ----------------------------------------------------------------------------
extern "C" void kernel_launch(void* const* d_in, const int* in_sizes, int n_in,
                              void* d_out, int out_size)
{
    const float* x     = (const float*)d_in[0];
    const float* w_in  = (const float*)d_in[1];
    const float* b_in  = (const float*)d_in[2];
    const float* w_out = (const float*)d_in[3];
    const float* b_out = (const float*)d_in[4];
    float* out = (float*)d_out;

    float *qkv, *attn;
    uint4 *xh, *xl, *ah, *al, *wih, *wil, *woh, *wol;
    cudaGetSymbolAddress((void**)&qkv, g_qkv);
    cudaGetSymbolAddress((void**)&attn, g_attn);
    cudaGetSymbolAddress((void**)&xh, g_xh);
    cudaGetSymbolAddress((void**)&xl, g_xl);
    cudaGetSymbolAddress((void**)&ah, g_ah);
    cudaGetSymbolAddress((void**)&al, g_al);
    cudaGetSymbolAddress((void**)&wih, g_wih);
    cudaGetSymbolAddress((void**)&wil, g_wil);
    cudaGetSymbolAddress((void**)&woh, g_woh);
    cudaGetSymbolAddress((void**)&wol, g_wol);

    static bool attr_set = false;
    if (!attr_set) {
        cudaFuncSetAttribute(gemm_pre, cudaFuncAttributeMaxDynamicSharedMemorySize,
                             GEMM_SMEM);
        cudaFuncSetAttribute(attn_mma, cudaFuncAttributeMaxDynamicSharedMemorySize,
                             ATTN_SMEM);
        attr_set = true;
    }

    // 0) Pre-split operands into fragment-major bf16 hi/lo
    prep_a<<<4096, 256>>>(x, xh, xl, En);
    prep_b<<<1536, 256>>>(w_in, wih, wil, En);

    // 1) QKV projection; K/V columns (tiles >= 8) pre-rounded to tf32
    {
        dim3 grid(24, 64);
        gemm_pre<<<grid, 256, GEMM_SMEM>>>(xh, xl, wih, wil, b_in, qkv,
                                           3 * En, En / 32, 8);
    }

    // 2) Causal flash attention (tf32, Q fragment-major, producer pipeline)
    {
        dim3 grid(Sn / ABQ, Hn, Bn);
        attn_mma<<<grid, 160, ATTN_SMEM>>>(qkv, attn);
    }

    // 3) Output projection
    prep_a<<<4096, 256>>>(attn, ah, al, En);
    prep_b<<<512, 256>>>(w_out, woh, wol, En);
    {
        dim3 grid(8, 64);
        gemm_pre<<<grid, 256, GEMM_SMEM>>>(ah, al, woh, wol, b_out, out,
                                           En, En / 32, 1 << 30);
    }
}